// round 5
// baseline (speedup 1.0000x reference)
#include <cuda_runtime.h>
#include <cuda_bf16.h>
#include <mma.h>

using namespace nvcuda;
typedef __nv_bfloat16 bf16;

// Problem constants
#define B_   2
#define T_   4096
#define H_   8
#define D_   64
#define C_   64                // tokens per sub-chunk
#define SC_  8                 // sub-chunks per superchunk
#define NSC_ 8                 // superchunks per (b,h)
#define BH_  16
#define ROWSTRIDE 512          // H_*D_
#define SB_  72                // bf16 smem row stride (LDSM conflict-free)

// Scratch: per-(bh, superchunk) DxD fp32 sums -> exclusive prefix. 2MB.
__device__ float g_S[(size_t)BH_ * NSC_ * D_ * D_];

typedef wmma::fragment<wmma::matrix_a, 16, 16, 16, bf16, wmma::row_major> FragAR;
typedef wmma::fragment<wmma::matrix_a, 16, 16, 16, bf16, wmma::col_major> FragAC;
typedef wmma::fragment<wmma::matrix_b, 16, 16, 16, bf16, wmma::row_major> FragBR;
typedef wmma::fragment<wmma::matrix_b, 16, 16, 16, bf16, wmma::col_major> FragBC;
typedef wmma::fragment<wmma::accumulator, 16, 16, 16, float> FragAcc;

// 3-term split mma: (ahi+alo)*(bhi+blo) ~= ahi*bhi + ahi*blo + alo*bhi
#define MMA3(acc, ahi, alo, bhi, blo)            \
    do {                                         \
        wmma::mma_sync(acc, ahi, bhi, acc);      \
        wmma::mma_sync(acc, ahi, blo, acc);      \
        wmma::mma_sync(acc, alo, bhi, acc);      \
    } while (0)

__device__ __forceinline__ void split_store4(bf16* HI, bf16* LO, int idx, float4 x) {
    float hx = __bfloat162float(__float2bfloat16(x.x));
    float hy = __bfloat162float(__float2bfloat16(x.y));
    float hz = __bfloat162float(__float2bfloat16(x.z));
    float hw = __bfloat162float(__float2bfloat16(x.w));
    __nv_bfloat162 h01 = __floats2bfloat162_rn(x.x, x.y);
    __nv_bfloat162 h23 = __floats2bfloat162_rn(x.z, x.w);
    __nv_bfloat162 l01 = __floats2bfloat162_rn(x.x - hx, x.y - hy);
    __nv_bfloat162 l23 = __floats2bfloat162_rn(x.z - hz, x.w - hw);
    uint2 hh, ll;
    hh.x = *(unsigned*)&h01; hh.y = *(unsigned*)&h23;
    ll.x = *(unsigned*)&l01; ll.y = *(unsigned*)&l23;
    *(uint2*)&HI[idx] = hh;
    *(uint2*)&LO[idx] = ll;
}

__device__ __forceinline__ void split_scalar(float x, bf16& hi, bf16& lo) {
    hi = __float2bfloat16(x);
    lo = __float2bfloat16(x - __bfloat162float(hi));
}

__device__ __forceinline__ void cp_async16(void* sdst, const void* gsrc) {
    unsigned s = (unsigned)__cvta_generic_to_shared(sdst);
    asm volatile("cp.async.cg.shared.global [%0], [%1], 16;" :: "r"(s), "l"(gsrc));
}
__device__ __forceinline__ void cp_commit() { asm volatile("cp.async.commit_group;"); }
__device__ __forceinline__ void cp_wait0()  { asm volatile("cp.async.wait_group 0;" ::: "memory"); }

// ---------------------------------------------------------------------------
// Kernel A: per (bh, superchunk): S = sum over 512 tokens of V^T K.
// cp.async staging, wmma accumulators persist across the 8 sub-chunks.
// ---------------------------------------------------------------------------
#define SMEMA_BYTES (2 * C_ * D_ * 4 + 4 * C_ * SB_ * 2)   // 69632

__global__ void __launch_bounds__(256) supersum_kernel(const float* __restrict__ k,
                                                       const float* __restrict__ v) {
    extern __shared__ __align__(16) char smA[];
    float* Kst = (float*)smA;                  // fp32 stage [64][64]
    float* Vst = Kst + C_ * D_;
    bf16* Khi = (bf16*)(Vst + C_ * D_);
    bf16* Klo = Khi + C_ * SB_;
    bf16* Vhi = Klo + C_ * SB_;
    bf16* Vlo = Vhi + C_ * SB_;

    int blk = blockIdx.x;                      // [0, 128)
    int bh = blk >> 3, sc = blk & 7;
    int b = bh >> 3, h = bh & 7;
    int tid = threadIdx.x;

    auto issue = [&](int j) {
        size_t tok0 = (size_t)(sc * SC_ + j) * C_;
        const float* kb = k + ((size_t)b * T_ + tok0) * ROWSTRIDE + h * D_;
        const float* vb = v + ((size_t)b * T_ + tok0) * ROWSTRIDE + h * D_;
        #pragma unroll
        for (int f = tid; f < C_ * D_ / 4; f += 256) {
            int s = f >> 4, c4 = f & 15;
            cp_async16(&Kst[f * 4], kb + (size_t)s * ROWSTRIDE + c4 * 4);
            cp_async16(&Vst[f * 4], vb + (size_t)s * ROWSTRIDE + c4 * 4);
        }
        cp_commit();
    };

    int wid = tid >> 5;
    int d0 = (wid >> 1) * 16;
    int e0 = (wid & 1) * 32;
    FragAcc acc0, acc1;
    wmma::fill_fragment(acc0, 0.f);
    wmma::fill_fragment(acc1, 0.f);

    issue(0);
    for (int j = 0; j < SC_; j++) {
        cp_wait0();
        __syncthreads();                       // stage ready; prev mma reads done
        #pragma unroll
        for (int f = tid; f < C_ * D_ / 4; f += 256) {
            int s = f >> 4, cc = (f & 15) * 4;
            split_store4(Khi, Klo, s * SB_ + cc, *(float4*)&Kst[f * 4]);
            split_store4(Vhi, Vlo, s * SB_ + cc, *(float4*)&Vst[f * 4]);
        }
        __syncthreads();                       // stage consumed, operands ready
        if (j + 1 < SC_) issue(j + 1);

        #pragma unroll
        for (int kk = 0; kk < 4; kk++) {
            int s0 = kk * 16;
            FragAC ahi, alo;
            wmma::load_matrix_sync(ahi, &Vhi[s0 * SB_ + d0], SB_);  // A(d,s)=V[s][d]
            wmma::load_matrix_sync(alo, &Vlo[s0 * SB_ + d0], SB_);
            FragBR bhi, blo;
            wmma::load_matrix_sync(bhi, &Khi[s0 * SB_ + e0], SB_);  // B(s,e)=K[s][e]
            wmma::load_matrix_sync(blo, &Klo[s0 * SB_ + e0], SB_);
            MMA3(acc0, ahi, alo, bhi, blo);
            wmma::load_matrix_sync(bhi, &Khi[s0 * SB_ + e0 + 16], SB_);
            wmma::load_matrix_sync(blo, &Klo[s0 * SB_ + e0 + 16], SB_);
            MMA3(acc1, ahi, alo, bhi, blo);
        }
    }

    float* Sout = g_S + (size_t)blk * D_ * D_;
    wmma::store_matrix_sync(&Sout[d0 * D_ + e0],      acc0, D_, wmma::mem_row_major);
    wmma::store_matrix_sync(&Sout[d0 * D_ + e0 + 16], acc1, D_, wmma::mem_row_major);
}

// ---------------------------------------------------------------------------
// Kernel B: exclusive prefix over the 8 superchunks per (bh, d, e).
// ---------------------------------------------------------------------------
__global__ void __launch_bounds__(256) prefix_kernel() {
    int gidx = blockIdx.x * 256 + threadIdx.x;   // [0, BH_*4096)
    int bh  = gidx >> 12;
    int idx = gidx & 4095;
    float* base = g_S + (size_t)bh * NSC_ * D_ * D_ + idx;

    float vals[NSC_];
    #pragma unroll
    for (int c = 0; c < NSC_; c++) vals[c] = base[(size_t)c * D_ * D_];
    float run = 0.f;
    #pragma unroll
    for (int c = 0; c < NSC_; c++) { float t = vals[c]; vals[c] = run; run += t; }
    #pragma unroll
    for (int c = 0; c < NSC_; c++) base[(size_t)c * D_ * D_] = vals[c];
}

// ---------------------------------------------------------------------------
// Kernel C: per (bh, superchunk): walk 8 sub-chunks sequentially.
// M carried in fp32 wmma accumulators; re-staged to bf16 hi/lo smem per step.
// Per sub-chunk: scores = QK^T, mask, y = A V + Q M^T, M += V^T K.
// ---------------------------------------------------------------------------
#define SMEMC_BYTES (3 * C_ * D_ * 4 + 10 * C_ * SB_ * 2 + C_ * SB_ * 4)  // 159744

__global__ void __launch_bounds__(256) fused_output_kernel(const float* __restrict__ q,
                                                           const float* __restrict__ k,
                                                           const float* __restrict__ v,
                                                           float* __restrict__ y) {
    extern __shared__ __align__(16) char smC[];
    float* Qst = (float*)smC;                  // fp32 stage [64][64] x3
    float* Kst = Qst + C_ * D_;
    float* Vst = Kst + C_ * D_;
    bf16* Qhi = (bf16*)(Vst + C_ * D_);
    bf16* Qlo = Qhi + C_ * SB_;
    bf16* Khi = Qlo + C_ * SB_;
    bf16* Klo = Khi + C_ * SB_;
    bf16* Vhi = Klo + C_ * SB_;
    bf16* Vlo = Vhi + C_ * SB_;
    bf16* Shi = Vlo + C_ * SB_;
    bf16* Slo = Shi + C_ * SB_;
    bf16* Mhi = Slo + C_ * SB_;
    bf16* Mlo = Mhi + C_ * SB_;
    float* Sraw = (float*)(Mlo + C_ * SB_);    // fp32 scratch [64][72]

    int blk = blockIdx.x;                      // [0, 128)
    int bh = blk >> 3, sc = blk & 7;
    int b = bh >> 3, h = bh & 7;
    int tid = threadIdx.x;
    int wid = tid >> 5;
    int t0 = (wid >> 1) * 16;                  // output-row group (also M d-rows)
    int n0 = (wid & 1) * 32;                   // output-col group (also M e-cols)

    // ---- init M from exclusive superchunk prefix ----
    const float* Mg = g_S + (size_t)blk * D_ * D_;
    #pragma unroll
    for (int f = tid; f < D_ * D_ / 4; f += 256)
        *(float4*)&Sraw[(f >> 4) * SB_ + (f & 15) * 4] = *(const float4*)(Mg + f * 4);
    __syncthreads();
    FragAcc accM0, accM1;
    wmma::load_matrix_sync(accM0, &Sraw[t0 * SB_ + n0],      SB_, wmma::mem_row_major);
    wmma::load_matrix_sync(accM1, &Sraw[t0 * SB_ + n0 + 16], SB_, wmma::mem_row_major);
    #pragma unroll
    for (int f = tid; f < D_ * D_ / 4; f += 256) {
        int d = f >> 4, cc = (f & 15) * 4;
        split_store4(Mhi, Mlo, d * SB_ + cc, *(float4*)&Sraw[d * SB_ + cc]);
    }

    auto issue = [&](int j) {
        size_t tok0 = (size_t)(sc * SC_ + j) * C_;
        const float* qb = q + ((size_t)b * T_ + tok0) * ROWSTRIDE + h * D_;
        const float* kb = k + ((size_t)b * T_ + tok0) * ROWSTRIDE + h * D_;
        const float* vb = v + ((size_t)b * T_ + tok0) * ROWSTRIDE + h * D_;
        #pragma unroll
        for (int f = tid; f < C_ * D_ / 4; f += 256) {
            int s = f >> 4, c4 = f & 15;
            cp_async16(&Qst[f * 4], qb + (size_t)s * ROWSTRIDE + c4 * 4);
            cp_async16(&Kst[f * 4], kb + (size_t)s * ROWSTRIDE + c4 * 4);
            cp_async16(&Vst[f * 4], vb + (size_t)s * ROWSTRIDE + c4 * 4);
        }
        cp_commit();
    };

    issue(0);
    for (int j = 0; j < SC_; j++) {
        cp_wait0();
        __syncthreads();                       // stage ready; prior-iter reads done
        #pragma unroll
        for (int f = tid; f < C_ * D_ / 4; f += 256) {
            int s = f >> 4, cc = (f & 15) * 4;
            split_store4(Qhi, Qlo, s * SB_ + cc, *(float4*)&Qst[f * 4]);
            split_store4(Khi, Klo, s * SB_ + cc, *(float4*)&Kst[f * 4]);
            split_store4(Vhi, Vlo, s * SB_ + cc, *(float4*)&Vst[f * 4]);
        }
        __syncthreads();
        if (j + 1 < SC_) issue(j + 1);

        // ---- scores: S[t][s] = sum_e Q[t][e] K[s][e] ----
        FragAcc acc0, acc1;
        wmma::fill_fragment(acc0, 0.f);
        wmma::fill_fragment(acc1, 0.f);
        #pragma unroll
        for (int kk = 0; kk < 4; kk++) {
            int e0 = kk * 16;
            FragAR ahi, alo;
            wmma::load_matrix_sync(ahi, &Qhi[t0 * SB_ + e0], SB_);
            wmma::load_matrix_sync(alo, &Qlo[t0 * SB_ + e0], SB_);
            FragBC bhi, blo;
            wmma::load_matrix_sync(bhi, &Khi[n0 * SB_ + e0], SB_);      // B(e,s)=K[s][e]
            wmma::load_matrix_sync(blo, &Klo[n0 * SB_ + e0], SB_);
            MMA3(acc0, ahi, alo, bhi, blo);
            wmma::load_matrix_sync(bhi, &Khi[(n0 + 16) * SB_ + e0], SB_);
            wmma::load_matrix_sync(blo, &Klo[(n0 + 16) * SB_ + e0], SB_);
            MMA3(acc1, ahi, alo, bhi, blo);
        }
        wmma::store_matrix_sync(&Sraw[t0 * SB_ + n0],      acc0, SB_, wmma::mem_row_major);
        wmma::store_matrix_sync(&Sraw[t0 * SB_ + n0 + 16], acc1, SB_, wmma::mem_row_major);
        __syncthreads();

        // ---- causal mask (s <= t) + bf16 split ----
        #pragma unroll
        for (int f = tid; f < C_ * D_; f += 256) {
            int t = f >> 6, s = f & 63;
            float x = (s <= t) ? Sraw[t * SB_ + s] : 0.f;
            bf16 hi, lo;
            split_scalar(x, hi, lo);
            Shi[t * SB_ + s] = hi;
            Slo[t * SB_ + s] = lo;
        }
        __syncthreads();

        // ---- y = A V + Q M^T ----
        wmma::fill_fragment(acc0, 0.f);
        wmma::fill_fragment(acc1, 0.f);
        #pragma unroll
        for (int kk = 0; kk < 4; kk++) {
            int s0 = kk * 16;
            FragAR ahi, alo;
            wmma::load_matrix_sync(ahi, &Shi[t0 * SB_ + s0], SB_);
            wmma::load_matrix_sync(alo, &Slo[t0 * SB_ + s0], SB_);
            FragBR bhi, blo;
            wmma::load_matrix_sync(bhi, &Vhi[s0 * SB_ + n0], SB_);
            wmma::load_matrix_sync(blo, &Vlo[s0 * SB_ + n0], SB_);
            MMA3(acc0, ahi, alo, bhi, blo);
            wmma::load_matrix_sync(bhi, &Vhi[s0 * SB_ + n0 + 16], SB_);
            wmma::load_matrix_sync(blo, &Vlo[s0 * SB_ + n0 + 16], SB_);
            MMA3(acc1, ahi, alo, bhi, blo);
        }
        #pragma unroll
        for (int kk = 0; kk < 4; kk++) {
            int e0 = kk * 16;
            FragAR ahi, alo;
            wmma::load_matrix_sync(ahi, &Qhi[t0 * SB_ + e0], SB_);
            wmma::load_matrix_sync(alo, &Qlo[t0 * SB_ + e0], SB_);
            FragBC bhi, blo;
            wmma::load_matrix_sync(bhi, &Mhi[n0 * SB_ + e0], SB_);      // B(e,d)=M[d][e]
            wmma::load_matrix_sync(blo, &Mlo[n0 * SB_ + e0], SB_);
            MMA3(acc0, ahi, alo, bhi, blo);
            wmma::load_matrix_sync(bhi, &Mhi[(n0 + 16) * SB_ + e0], SB_);
            wmma::load_matrix_sync(blo, &Mlo[(n0 + 16) * SB_ + e0], SB_);
            MMA3(acc1, ahi, alo, bhi, blo);
        }
        {
            size_t tok0 = (size_t)(sc * SC_ + j) * C_;
            float* yb = y + ((size_t)b * T_ + tok0) * ROWSTRIDE + h * D_;
            wmma::store_matrix_sync(yb + (size_t)t0 * ROWSTRIDE + n0,      acc0,
                                    ROWSTRIDE, wmma::mem_row_major);
            wmma::store_matrix_sync(yb + (size_t)t0 * ROWSTRIDE + n0 + 16, acc1,
                                    ROWSTRIDE, wmma::mem_row_major);
        }

        // ---- M += V^T K ----
        #pragma unroll
        for (int kk = 0; kk < 4; kk++) {
            int s0 = kk * 16;
            FragAC ahi, alo;
            wmma::load_matrix_sync(ahi, &Vhi[s0 * SB_ + t0], SB_);      // A(d,s)=V[s][d]
            wmma::load_matrix_sync(alo, &Vlo[s0 * SB_ + t0], SB_);
            FragBR bhi, blo;
            wmma::load_matrix_sync(bhi, &Khi[s0 * SB_ + n0], SB_);      // B(s,e)=K[s][e]
            wmma::load_matrix_sync(blo, &Klo[s0 * SB_ + n0], SB_);
            MMA3(accM0, ahi, alo, bhi, blo);
            wmma::load_matrix_sync(bhi, &Khi[s0 * SB_ + n0 + 16], SB_);
            wmma::load_matrix_sync(blo, &Klo[s0 * SB_ + n0 + 16], SB_);
            MMA3(accM1, ahi, alo, bhi, blo);
        }

        // ---- re-stage M to bf16 hi/lo for next sub-chunk ----
        if (j + 1 < SC_) {
            __syncthreads();                   // all QM reads of Mhi/Mlo done
            wmma::store_matrix_sync(&Sraw[t0 * SB_ + n0],      accM0, SB_,
                                    wmma::mem_row_major);
            wmma::store_matrix_sync(&Sraw[t0 * SB_ + n0 + 16], accM1, SB_,
                                    wmma::mem_row_major);
            __syncthreads();
            #pragma unroll
            for (int f = tid; f < D_ * D_ / 4; f += 256) {
                int d = f >> 4, cc = (f & 15) * 4;
                split_store4(Mhi, Mlo, d * SB_ + cc, *(float4*)&Sraw[d * SB_ + cc]);
            }
        }
    }
}

// ---------------------------------------------------------------------------
extern "C" void kernel_launch(void* const* d_in, const int* in_sizes, int n_in,
                              void* d_out, int out_size) {
    (void)in_sizes; (void)n_in; (void)out_size;
    const float* q = (const float*)d_in[0];
    const float* k = (const float*)d_in[1];
    const float* v = (const float*)d_in[2];
    float* y = (float*)d_out;

    cudaFuncSetAttribute(supersum_kernel, cudaFuncAttributeMaxDynamicSharedMemorySize,
                         SMEMA_BYTES);
    cudaFuncSetAttribute(fused_output_kernel, cudaFuncAttributeMaxDynamicSharedMemorySize,
                         SMEMC_BYTES);

    supersum_kernel<<<BH_ * NSC_, 256, SMEMA_BYTES>>>(k, v);
    prefix_kernel<<<(BH_ * D_ * D_) / 256, 256>>>();
    fused_output_kernel<<<BH_ * NSC_, 256, SMEMC_BYTES>>>(q, k, v, y);
}

// round 6
// speedup vs baseline: 2.0029x; 2.0029x over previous
#include <cuda_runtime.h>
#include <cuda_fp16.h>
#include <mma.h>

using namespace nvcuda;

// Problem constants
#define B_  2
#define T_  4096
#define H_  8
#define D_  64
#define C_  64
#define NC_ (T_/C_)            // 64
#define BH_ (B_*H_)            // 16
#define ROWSTRIDE 512          // H_*D_
#define SB_ 72                 // fp16 smem row stride (144B -> LDSM conflict-free)

// Scratch: per-(bh,chunk) DxD fp32 matrix (pass1 sums -> pass2 exclusive prefix). 16MB.
__device__ float g_S[(size_t)BH_ * NC_ * D_ * D_];

typedef wmma::fragment<wmma::matrix_a, 16, 16, 16, __half, wmma::row_major> FragAR;
typedef wmma::fragment<wmma::matrix_a, 16, 16, 16, __half, wmma::col_major> FragAC;
typedef wmma::fragment<wmma::matrix_b, 16, 16, 16, __half, wmma::row_major> FragBR;
typedef wmma::fragment<wmma::matrix_b, 16, 16, 16, __half, wmma::col_major> FragBC;
typedef wmma::fragment<wmma::accumulator, 16, 16, 16, float> FragAcc;

// 2-term split mma on A only: (ahi+alo)*b
#define MMA2(acc, ahi, alo, b)              \
    do {                                    \
        wmma::mma_sync(acc, ahi, b, acc);   \
        wmma::mma_sync(acc, alo, b, acc);   \
    } while (0)

// Split 4 fp32 into fp16 hi/lo quads and store (8B stores).
__device__ __forceinline__ void splitA_store4(__half* HI, __half* LO, int idx, float4 x) {
    __half hx = __float2half_rn(x.x);
    __half hy = __float2half_rn(x.y);
    __half hz = __float2half_rn(x.z);
    __half hw = __float2half_rn(x.w);
    __half2 h01 = __halves2half2(hx, hy);
    __half2 h23 = __halves2half2(hz, hw);
    __half2 l01 = __floats2half2_rn(x.x - __half2float(hx), x.y - __half2float(hy));
    __half2 l23 = __floats2half2_rn(x.z - __half2float(hz), x.w - __half2float(hw));
    uint2 hh, ll;
    hh.x = *(unsigned*)&h01; hh.y = *(unsigned*)&h23;
    ll.x = *(unsigned*)&l01; ll.y = *(unsigned*)&l23;
    *(uint2*)&HI[idx] = hh;
    *(uint2*)&LO[idx] = ll;
}

// Quantize 4 fp32 to fp16 and store.
__device__ __forceinline__ void quant_store4(__half* Bq, int idx, float4 x) {
    __half2 h01 = __floats2half2_rn(x.x, x.y);
    __half2 h23 = __floats2half2_rn(x.z, x.w);
    uint2 hh;
    hh.x = *(unsigned*)&h01; hh.y = *(unsigned*)&h23;
    *(uint2*)&Bq[idx] = hh;
}

// ---------------------------------------------------------------------------
// Pass 1: S[d][e] = sum_s V[s][d] * K[s][e]  per (bh, chunk).
// 128 threads = 4 warps; warp wid covers rows d0=wid*16, ALL 64 cols (4 accs).
// A = V^T split (col-major), B = K quantized fp16 (row-major).
// ---------------------------------------------------------------------------
#define SMEM1_BYTES (3 * C_ * SB_ * (int)sizeof(__half))   // 27648

__global__ void __launch_bounds__(128) chunk_sum_kernel(const float* __restrict__ k,
                                                        const float* __restrict__ v) {
    extern __shared__ __align__(16) char smraw1[];
    __half* Vhi = (__half*)smraw1;
    __half* Vlo = Vhi + C_ * SB_;
    __half* K16 = Vlo + C_ * SB_;

    int blk = blockIdx.x;             // [0, 1024)
    int bh  = blk >> 6;
    int c   = blk & (NC_ - 1);
    int b   = bh >> 3, h = bh & 7;
    int tid = threadIdx.x;

    const float* kbase = k + (((size_t)b * T_ + (size_t)c * C_) * H_ + h) * D_;
    const float* vbase = v + (((size_t)b * T_ + (size_t)c * C_) * H_ + h) * D_;

    #pragma unroll
    for (int f = tid; f < C_ * D_ / 4; f += 128) {
        int s = f >> 4;
        int cc = (f & 15) * 4;
        quant_store4(K16, s * SB_ + cc,
                     *(const float4*)(kbase + (size_t)s * ROWSTRIDE + cc));
        splitA_store4(Vhi, Vlo, s * SB_ + cc,
                      *(const float4*)(vbase + (size_t)s * ROWSTRIDE + cc));
    }
    __syncthreads();

    int wid = tid >> 5;
    int d0 = wid * 16;

    FragAcc acc[4];
    #pragma unroll
    for (int j = 0; j < 4; j++) wmma::fill_fragment(acc[j], 0.f);

    #pragma unroll
    for (int kk = 0; kk < 4; kk++) {
        int s0 = kk * 16;
        FragAC ahi, alo;
        wmma::load_matrix_sync(ahi, &Vhi[s0 * SB_ + d0], SB_);   // A(d,s)=V[s][d]
        wmma::load_matrix_sync(alo, &Vlo[s0 * SB_ + d0], SB_);
        #pragma unroll
        for (int j = 0; j < 4; j++) {
            FragBR bq;
            wmma::load_matrix_sync(bq, &K16[s0 * SB_ + j * 16], SB_); // B(s,e)=K[s][e]
            MMA2(acc[j], ahi, alo, bq);
        }
    }

    float* Sout = g_S + (size_t)blk * D_ * D_;
    #pragma unroll
    for (int j = 0; j < 4; j++)
        wmma::store_matrix_sync(&Sout[d0 * D_ + j * 16], acc[j], D_, wmma::mem_row_major);
}

// ---------------------------------------------------------------------------
// Pass 2: in-place EXCLUSIVE prefix over the chunk axis for every (bh, d, e).
// ---------------------------------------------------------------------------
__global__ void __launch_bounds__(256) prefix_kernel() {
    int gidx = blockIdx.x * 256 + threadIdx.x;   // [0, BH_*4096)
    int bh  = gidx >> 12;
    int idx = gidx & 4095;
    float* base = g_S + (size_t)bh * NC_ * D_ * D_ + idx;

    float vals[NC_];
    #pragma unroll
    for (int c = 0; c < NC_; c++) vals[c] = base[(size_t)c * D_ * D_];
    float run = 0.f;
    #pragma unroll
    for (int c = 0; c < NC_; c++) { float t = vals[c]; vals[c] = run; run += t; }
    #pragma unroll
    for (int c = 0; c < NC_; c++) base[(size_t)c * D_ * D_] = vals[c];
}

// ---------------------------------------------------------------------------
// Pass 3: Y = tril(Q K^T) V + Q M_prev^T per (bh, chunk).
// 128 threads = 4 warps; warp wid: rows t0=wid*16, ALL 64 cols (4 accs/phase).
// Buffers: Qhi Qlo K16 V16 Shi Slo  +  R region: fp32 Sraw -> fp16 M16.
// ---------------------------------------------------------------------------
#define HBUF_ (C_ * SB_)                                   // 4608 halves
#define SMEM3_BYTES (6 * HBUF_ * 2 + C_ * SB_ * 4)         // 55296 + 18432 = 73728

__global__ void __launch_bounds__(128) output_kernel(const float* __restrict__ q,
                                                     const float* __restrict__ k,
                                                     const float* __restrict__ v,
                                                     float* __restrict__ y) {
    extern __shared__ __align__(16) char smraw[];
    __half* Qhi = (__half*)smraw;
    __half* Qlo = Qhi + HBUF_;
    __half* K16 = Qlo + HBUF_;
    __half* V16 = K16 + HBUF_;
    __half* Shi = V16 + HBUF_;
    __half* Slo = Shi + HBUF_;
    float*  Sraw = (float*)(Slo + HBUF_);   // fp32 [64][72] scratch
    __half* M16 = (__half*)Sraw;            // later reuses the same region

    int blk = blockIdx.x;             // [0, 1024)
    int bh  = blk >> 6;
    int c   = blk & (NC_ - 1);
    int b   = bh >> 3, h = bh & 7;
    int tid = threadIdx.x;

    const float* qbase = q + (((size_t)b * T_ + (size_t)c * C_) * H_ + h) * D_;
    const float* kbase = k + (((size_t)b * T_ + (size_t)c * C_) * H_ + h) * D_;
    const float* vbase = v + (((size_t)b * T_ + (size_t)c * C_) * H_ + h) * D_;
    const float* Mbase = g_S + (size_t)blk * D_ * D_;

    #pragma unroll
    for (int f = tid; f < C_ * D_ / 4; f += 128) {
        int s = f >> 4;
        int cc = (f & 15) * 4;
        splitA_store4(Qhi, Qlo, s * SB_ + cc,
                      *(const float4*)(qbase + (size_t)s * ROWSTRIDE + cc));
        quant_store4(K16, s * SB_ + cc,
                     *(const float4*)(kbase + (size_t)s * ROWSTRIDE + cc));
        quant_store4(V16, s * SB_ + cc,
                     *(const float4*)(vbase + (size_t)s * ROWSTRIDE + cc));
    }
    __syncthreads();

    int wid = tid >> 5;
    int t0 = wid * 16;

    FragAcc acc[4];
    #pragma unroll
    for (int j = 0; j < 4; j++) wmma::fill_fragment(acc[j], 0.f);

    // ---- Scores: S[t][s] = sum_e Q[t][e] K[s][e];  B = K^T (col-major)
    #pragma unroll
    for (int kk = 0; kk < 4; kk++) {
        int e0 = kk * 16;
        FragAR ahi, alo;
        wmma::load_matrix_sync(ahi, &Qhi[t0 * SB_ + e0], SB_);
        wmma::load_matrix_sync(alo, &Qlo[t0 * SB_ + e0], SB_);
        #pragma unroll
        for (int j = 0; j < 4; j++) {
            FragBC bq;
            wmma::load_matrix_sync(bq, &K16[(j * 16) * SB_ + e0], SB_); // B(e,s)=K[s][e]
            MMA2(acc[j], ahi, alo, bq);
        }
    }
    #pragma unroll
    for (int j = 0; j < 4; j++)
        wmma::store_matrix_sync(&Sraw[t0 * SB_ + j * 16], acc[j], SB_, wmma::mem_row_major);
    __syncthreads();

    // ---- Causal mask (s <= t) + fp16 split into Shi/Slo (2 elems per iter)
    #pragma unroll
    for (int f = tid; f < C_ * D_ / 2; f += 128) {
        int t = f >> 5;
        int sp = (f & 31) * 2;
        float v0 = (sp     <= t) ? Sraw[t * SB_ + sp]     : 0.f;
        float v1 = (sp + 1 <= t) ? Sraw[t * SB_ + sp + 1] : 0.f;
        __half h0 = __float2half_rn(v0);
        __half h1 = __float2half_rn(v1);
        *(__half2*)&Shi[t * SB_ + sp] = __halves2half2(h0, h1);
        *(__half2*)&Slo[t * SB_ + sp] =
            __floats2half2_rn(v0 - __half2float(h0), v1 - __half2float(h1));
    }
    __syncthreads();   // all Sraw reads done before M16 overwrites the region

    // ---- Load M (exclusive prefix), quantize fp16 into the freed region
    #pragma unroll
    for (int f = tid; f < D_ * D_ / 4; f += 128) {
        int d = f >> 4;
        int cc = (f & 15) * 4;
        quant_store4(M16, d * SB_ + cc, *(const float4*)(Mbase + f * 4));
    }
    __syncthreads();

    // ---- Y = A V + Q M^T
    #pragma unroll
    for (int j = 0; j < 4; j++) wmma::fill_fragment(acc[j], 0.f);

    #pragma unroll
    for (int kk = 0; kk < 4; kk++) {
        int s0 = kk * 16;
        FragAR ahi, alo;
        wmma::load_matrix_sync(ahi, &Shi[t0 * SB_ + s0], SB_);
        wmma::load_matrix_sync(alo, &Slo[t0 * SB_ + s0], SB_);
        #pragma unroll
        for (int j = 0; j < 4; j++) {
            FragBR bq;
            wmma::load_matrix_sync(bq, &V16[s0 * SB_ + j * 16], SB_);  // B(s,d)=V[s][d]
            MMA2(acc[j], ahi, alo, bq);
        }
    }
    #pragma unroll
    for (int kk = 0; kk < 4; kk++) {
        int e0 = kk * 16;
        FragAR ahi, alo;
        wmma::load_matrix_sync(ahi, &Qhi[t0 * SB_ + e0], SB_);
        wmma::load_matrix_sync(alo, &Qlo[t0 * SB_ + e0], SB_);
        #pragma unroll
        for (int j = 0; j < 4; j++) {
            FragBC bq;
            wmma::load_matrix_sync(bq, &M16[(j * 16) * SB_ + e0], SB_); // B(e,d)=M[d][e]
            MMA2(acc[j], ahi, alo, bq);
        }
    }

    float* ybase = y + (((size_t)b * T_ + (size_t)c * C_) * H_ + h) * D_;
    #pragma unroll
    for (int j = 0; j < 4; j++)
        wmma::store_matrix_sync(ybase + (size_t)t0 * ROWSTRIDE + j * 16, acc[j],
                                ROWSTRIDE, wmma::mem_row_major);
}

// ---------------------------------------------------------------------------
extern "C" void kernel_launch(void* const* d_in, const int* in_sizes, int n_in,
                              void* d_out, int out_size) {
    (void)in_sizes; (void)n_in; (void)out_size;
    const float* q = (const float*)d_in[0];
    const float* k = (const float*)d_in[1];
    const float* v = (const float*)d_in[2];
    float* y = (float*)d_out;

    cudaFuncSetAttribute(chunk_sum_kernel, cudaFuncAttributeMaxDynamicSharedMemorySize,
                         SMEM1_BYTES);
    cudaFuncSetAttribute(output_kernel, cudaFuncAttributeMaxDynamicSharedMemorySize,
                         SMEM3_BYTES);

    chunk_sum_kernel<<<BH_ * NC_, 128, SMEM1_BYTES>>>(k, v);
    prefix_kernel<<<(BH_ * D_ * D_) / 256, 256>>>();
    output_kernel<<<BH_ * NC_, 128, SMEM3_BYTES>>>(q, k, v, y);
}

// round 7
// speedup vs baseline: 2.0987x; 1.0478x over previous
#include <cuda_runtime.h>
#include <cuda_fp16.h>
#include <mma.h>

using namespace nvcuda;

// Problem constants
#define B_  2
#define T_  4096
#define H_  8
#define D_  64
#define C_  64
#define NC_ (T_/C_)            // 64
#define BH_ (B_*H_)            // 16
#define ROWSTRIDE 512          // H_*D_
#define SB_ 72                 // fp16 smem row stride (144B -> LDSM conflict-free)

// Scratch: fp16 chunk sums and fp16 exclusive-prefix state. 8MB each, L2-resident.
__device__ __half g_Sh[(size_t)BH_ * NC_ * D_ * D_];
__device__ __half g_M [(size_t)BH_ * NC_ * D_ * D_];

typedef wmma::fragment<wmma::matrix_a, 16, 16, 16, __half, wmma::row_major> FragAR;
typedef wmma::fragment<wmma::matrix_a, 16, 16, 16, __half, wmma::col_major> FragAC;
typedef wmma::fragment<wmma::matrix_b, 16, 16, 16, __half, wmma::row_major> FragBR;
typedef wmma::fragment<wmma::matrix_b, 16, 16, 16, __half, wmma::col_major> FragBC;
typedef wmma::fragment<wmma::accumulator, 16, 16, 16, float> FragAcc;

// 2-term split mma on A only: (ahi+alo)*b
#define MMA2(acc, ahi, alo, b)              \
    do {                                    \
        wmma::mma_sync(acc, ahi, b, acc);   \
        wmma::mma_sync(acc, alo, b, acc);   \
    } while (0)

// Split 4 fp32 into fp16 hi/lo quads and store (8B stores).
__device__ __forceinline__ void splitA_store4(__half* HI, __half* LO, int idx, float4 x) {
    __half hx = __float2half_rn(x.x);
    __half hy = __float2half_rn(x.y);
    __half hz = __float2half_rn(x.z);
    __half hw = __float2half_rn(x.w);
    __half2 h01 = __halves2half2(hx, hy);
    __half2 h23 = __halves2half2(hz, hw);
    __half2 l01 = __floats2half2_rn(x.x - __half2float(hx), x.y - __half2float(hy));
    __half2 l23 = __floats2half2_rn(x.z - __half2float(hz), x.w - __half2float(hw));
    uint2 hh, ll;
    hh.x = *(unsigned*)&h01; hh.y = *(unsigned*)&h23;
    ll.x = *(unsigned*)&l01; ll.y = *(unsigned*)&l23;
    *(uint2*)&HI[idx] = hh;
    *(uint2*)&LO[idx] = ll;
}

// Quantize 4 fp32 to fp16 and store.
__device__ __forceinline__ void quant_store4(__half* Bq, int idx, float4 x) {
    __half2 h01 = __floats2half2_rn(x.x, x.y);
    __half2 h23 = __floats2half2_rn(x.z, x.w);
    uint2 hh;
    hh.x = *(unsigned*)&h01; hh.y = *(unsigned*)&h23;
    *(uint2*)&Bq[idx] = hh;
}

__device__ __forceinline__ void cp_async16(void* sdst, const void* gsrc) {
    unsigned s = (unsigned)__cvta_generic_to_shared(sdst);
    asm volatile("cp.async.cg.shared.global [%0], [%1], 16;" :: "r"(s), "l"(gsrc));
}
__device__ __forceinline__ void cp_commit() { asm volatile("cp.async.commit_group;"); }
__device__ __forceinline__ void cp_wait0()  { asm volatile("cp.async.wait_group 0;" ::: "memory"); }

// ---------------------------------------------------------------------------
// Pass 1: S[d][e] = sum_s V[s][d] * K[s][e]  per (bh, chunk); S written fp16.
// 128 threads = 4 warps; warp wid: rows d0=wid*16, ALL 64 cols (4 accs).
// ---------------------------------------------------------------------------
#define SMEM1_BYTES (3 * C_ * SB_ * (int)sizeof(__half))   // 27648
#define SRW_ 68                                            // fp32 staging stride

__global__ void __launch_bounds__(128) chunk_sum_kernel(const float* __restrict__ k,
                                                        const float* __restrict__ v) {
    extern __shared__ __align__(16) char smraw1[];
    __half* Vhi = (__half*)smraw1;
    __half* Vlo = Vhi + C_ * SB_;
    __half* K16 = Vlo + C_ * SB_;
    float*  Sraw = (float*)smraw1;   // reuses Vhi+Vlo region after mma loop (17408B < 18432B)

    int blk = blockIdx.x;             // [0, 1024)
    int bh  = blk >> 6;
    int c   = blk & (NC_ - 1);
    int b   = bh >> 3, h = bh & 7;
    int tid = threadIdx.x;

    const float* kbase = k + (((size_t)b * T_ + (size_t)c * C_) * H_ + h) * D_;
    const float* vbase = v + (((size_t)b * T_ + (size_t)c * C_) * H_ + h) * D_;

    #pragma unroll
    for (int f = tid; f < C_ * D_ / 4; f += 128) {
        int s = f >> 4;
        int cc = (f & 15) * 4;
        quant_store4(K16, s * SB_ + cc,
                     *(const float4*)(kbase + (size_t)s * ROWSTRIDE + cc));
        splitA_store4(Vhi, Vlo, s * SB_ + cc,
                      *(const float4*)(vbase + (size_t)s * ROWSTRIDE + cc));
    }
    __syncthreads();

    int wid = tid >> 5;
    int d0 = wid * 16;

    FragAcc acc[4];
    #pragma unroll
    for (int j = 0; j < 4; j++) wmma::fill_fragment(acc[j], 0.f);

    #pragma unroll
    for (int kk = 0; kk < 4; kk++) {
        int s0 = kk * 16;
        FragAC ahi, alo;
        wmma::load_matrix_sync(ahi, &Vhi[s0 * SB_ + d0], SB_);   // A(d,s)=V[s][d]
        wmma::load_matrix_sync(alo, &Vlo[s0 * SB_ + d0], SB_);
        #pragma unroll
        for (int j = 0; j < 4; j++) {
            FragBR bq;
            wmma::load_matrix_sync(bq, &K16[s0 * SB_ + j * 16], SB_); // B(s,e)=K[s][e]
            MMA2(acc[j], ahi, alo, bq);
        }
    }
    __syncthreads();   // all LDSM reads done before Sraw overwrites the region

    #pragma unroll
    for (int j = 0; j < 4; j++)
        wmma::store_matrix_sync(&Sraw[d0 * SRW_ + j * 16], acc[j], SRW_, wmma::mem_row_major);
    __syncthreads();

    // fp16 pack + coalesced write (8B per 4 elems)
    __half* Sout = g_Sh + (size_t)blk * D_ * D_;
    #pragma unroll
    for (int f = tid; f < C_ * D_ / 4; f += 128) {
        int r = f >> 4;
        int cc = (f & 15) * 4;
        quant_store4(Sout, f * 4, *(const float4*)&Sraw[r * SRW_ + cc]);
    }
}

// ---------------------------------------------------------------------------
// Pass 2: exclusive prefix over the chunk axis; fp16 in (S), fp16 out (M).
// Each thread owns a half2 column pair; 64 loads batched for MLP.
// ---------------------------------------------------------------------------
__global__ void __launch_bounds__(256) prefix_kernel() {
    int gidx = blockIdx.x * 256 + threadIdx.x;   // [0, BH_*2048)
    int bh   = gidx >> 11;
    int pidx = gidx & 2047;
    const __half2* src = (const __half2*)g_Sh + (size_t)bh * NC_ * 2048 + pidx;
    __half2*       dst = (__half2*)g_M  + (size_t)bh * NC_ * 2048 + pidx;

    __half2 vals[NC_];
    #pragma unroll
    for (int c = 0; c < NC_; c++) vals[c] = src[(size_t)c * 2048];
    float rx = 0.f, ry = 0.f;
    #pragma unroll
    for (int c = 0; c < NC_; c++) {
        float2 t = __half22float2(vals[c]);
        dst[(size_t)c * 2048] = __floats2half2_rn(rx, ry);
        rx += t.x; ry += t.y;
    }
}

// ---------------------------------------------------------------------------
// Pass 3: Y = tril(Q K^T) V + Q M_prev^T per (bh, chunk).
// 128 threads = 4 warps; warp wid: rows t0=wid*16, ALL 64 cols (4 accs/phase).
// Buffers: Qhi Qlo K16 V16 Shi Slo + R region: fp32 Sraw -> fp16 M16 (cp.async).
// ---------------------------------------------------------------------------
#define HBUF_ (C_ * SB_)                                   // 4608 halves
#define SMEM3_BYTES (6 * HBUF_ * 2 + C_ * SB_ * 4)         // 73728

__global__ void __launch_bounds__(128) output_kernel(const float* __restrict__ q,
                                                     const float* __restrict__ k,
                                                     const float* __restrict__ v,
                                                     float* __restrict__ y) {
    extern __shared__ __align__(16) char smraw[];
    __half* Qhi = (__half*)smraw;
    __half* Qlo = Qhi + HBUF_;
    __half* K16 = Qlo + HBUF_;
    __half* V16 = K16 + HBUF_;
    __half* Shi = V16 + HBUF_;
    __half* Slo = Shi + HBUF_;
    float*  Sraw = (float*)(Slo + HBUF_);   // fp32 [64][72] scratch
    __half* M16 = (__half*)Sraw;            // later reuses the same region

    int blk = blockIdx.x;             // [0, 1024)
    int bh  = blk >> 6;
    int c   = blk & (NC_ - 1);
    int b   = bh >> 3, h = bh & 7;
    int tid = threadIdx.x;

    const float* qbase = q + (((size_t)b * T_ + (size_t)c * C_) * H_ + h) * D_;
    const float* kbase = k + (((size_t)b * T_ + (size_t)c * C_) * H_ + h) * D_;
    const float* vbase = v + (((size_t)b * T_ + (size_t)c * C_) * H_ + h) * D_;
    const __half* Mg = g_M + (size_t)blk * D_ * D_;

    #pragma unroll
    for (int f = tid; f < C_ * D_ / 4; f += 128) {
        int s = f >> 4;
        int cc = (f & 15) * 4;
        splitA_store4(Qhi, Qlo, s * SB_ + cc,
                      *(const float4*)(qbase + (size_t)s * ROWSTRIDE + cc));
        quant_store4(K16, s * SB_ + cc,
                     *(const float4*)(kbase + (size_t)s * ROWSTRIDE + cc));
        quant_store4(V16, s * SB_ + cc,
                     *(const float4*)(vbase + (size_t)s * ROWSTRIDE + cc));
    }
    __syncthreads();

    int wid = tid >> 5;
    int t0 = wid * 16;

    FragAcc acc[4];
    #pragma unroll
    for (int j = 0; j < 4; j++) wmma::fill_fragment(acc[j], 0.f);

    // ---- Scores: S[t][s] = sum_e Q[t][e] K[s][e];  B = K^T (col-major)
    #pragma unroll
    for (int kk = 0; kk < 4; kk++) {
        int e0 = kk * 16;
        FragAR ahi, alo;
        wmma::load_matrix_sync(ahi, &Qhi[t0 * SB_ + e0], SB_);
        wmma::load_matrix_sync(alo, &Qlo[t0 * SB_ + e0], SB_);
        #pragma unroll
        for (int j = 0; j < 4; j++) {
            FragBC bq;
            wmma::load_matrix_sync(bq, &K16[(j * 16) * SB_ + e0], SB_); // B(e,s)=K[s][e]
            MMA2(acc[j], ahi, alo, bq);
        }
    }
    #pragma unroll
    for (int j = 0; j < 4; j++)
        wmma::store_matrix_sync(&Sraw[t0 * SB_ + j * 16], acc[j], SB_, wmma::mem_row_major);
    __syncthreads();

    // ---- Causal mask (s <= t) + fp16 split into Shi/Slo
    #pragma unroll
    for (int f = tid; f < C_ * D_ / 2; f += 128) {
        int t = f >> 5;
        int sp = (f & 31) * 2;
        float v0 = (sp     <= t) ? Sraw[t * SB_ + sp]     : 0.f;
        float v1 = (sp + 1 <= t) ? Sraw[t * SB_ + sp + 1] : 0.f;
        __half h0 = __float2half_rn(v0);
        __half h1 = __float2half_rn(v1);
        *(__half2*)&Shi[t * SB_ + sp] = __halves2half2(h0, h1);
        *(__half2*)&Slo[t * SB_ + sp] =
            __floats2half2_rn(v0 - __half2float(h0), v1 - __half2float(h1));
    }
    __syncthreads();   // all Sraw reads done before M16 overwrites the region

    // ---- cp.async M (fp16 plane, L2-resident) into the freed region
    #pragma unroll
    for (int f = tid; f < D_ * D_ / 8; f += 128) {
        int d = f >> 3;
        int c8 = (f & 7) * 8;
        cp_async16(&M16[d * SB_ + c8], Mg + d * D_ + c8);
    }
    cp_commit();
    cp_wait0();
    __syncthreads();

    // ---- Y = A V + Q M^T
    #pragma unroll
    for (int j = 0; j < 4; j++) wmma::fill_fragment(acc[j], 0.f);

    #pragma unroll
    for (int kk = 0; kk < 4; kk++) {
        int s0 = kk * 16;
        FragAR ahi, alo;
        wmma::load_matrix_sync(ahi, &Shi[t0 * SB_ + s0], SB_);
        wmma::load_matrix_sync(alo, &Slo[t0 * SB_ + s0], SB_);
        #pragma unroll
        for (int j = 0; j < 4; j++) {
            FragBR bq;
            wmma::load_matrix_sync(bq, &V16[s0 * SB_ + j * 16], SB_);  // B(s,d)=V[s][d]
            MMA2(acc[j], ahi, alo, bq);
        }
    }
    #pragma unroll
    for (int kk = 0; kk < 4; kk++) {
        int e0 = kk * 16;
        FragAR ahi, alo;
        wmma::load_matrix_sync(ahi, &Qhi[t0 * SB_ + e0], SB_);
        wmma::load_matrix_sync(alo, &Qlo[t0 * SB_ + e0], SB_);
        #pragma unroll
        for (int j = 0; j < 4; j++) {
            FragBC bq;
            wmma::load_matrix_sync(bq, &M16[(j * 16) * SB_ + e0], SB_); // B(e,d)=M[d][e]
            MMA2(acc[j], ahi, alo, bq);
        }
    }

    float* ybase = y + (((size_t)b * T_ + (size_t)c * C_) * H_ + h) * D_;
    #pragma unroll
    for (int j = 0; j < 4; j++)
        wmma::store_matrix_sync(ybase + (size_t)t0 * ROWSTRIDE + j * 16, acc[j],
                                ROWSTRIDE, wmma::mem_row_major);
}

// ---------------------------------------------------------------------------
extern "C" void kernel_launch(void* const* d_in, const int* in_sizes, int n_in,
                              void* d_out, int out_size) {
    (void)in_sizes; (void)n_in; (void)out_size;
    const float* q = (const float*)d_in[0];
    const float* k = (const float*)d_in[1];
    const float* v = (const float*)d_in[2];
    float* y = (float*)d_out;

    cudaFuncSetAttribute(chunk_sum_kernel, cudaFuncAttributeMaxDynamicSharedMemorySize,
                         SMEM1_BYTES);
    cudaFuncSetAttribute(output_kernel, cudaFuncAttributeMaxDynamicSharedMemorySize,
                         SMEM3_BYTES);

    chunk_sum_kernel<<<BH_ * NC_, 128, SMEM1_BYTES>>>(k, v);
    prefix_kernel<<<(BH_ * 2048) / 256, 256>>>();
    output_kernel<<<BH_ * NC_, 128, SMEM3_BYTES>>>(q, k, v, y);
}